// round 12
// baseline (speedup 1.0000x reference)
#include <cuda_runtime.h>
#include <math.h>

#define GAMMA 0.99f
#define TAUF  0.95f

constexpr int THREADS = 256;
constexpr int ITEMS   = 4;
constexpr int CHUNK   = THREADS * ITEMS;   // 1024
constexpr int NWARPS  = THREADS / 32;      // 8
constexpr int PER     = 16;                // summaries per thread in fused pass2
constexpr int NB_MAX  = THREADS * PER;     // 4096 blocks max (B <= 4,194,304)

// Scratch (device globals; no allocation allowed)
__device__ float4 g_blk[NB_MAX];     // per-block affine summary: (a_vt, b_vt, a_A, b_A)
__device__ float2 g_carry[NB_MAX];   // per-block incoming carry VALUES (vt, A)
__device__ float4 g_mA[NB_MAX];      // per-block (SP, SG, SPP, SPG)
__device__ float  g_mB[NB_MAX];      // per-block SGG
__device__ unsigned char g_bits[NB_MAX * THREADS];  // packed masks, 1 byte per thread-tile
__device__ float2 g_normc;           // (mean, inv_std)
__device__ unsigned int g_done = 0;  // finish counter (reset by last block)

__device__ __forceinline__ float4 ident4() { return make_float4(1.f, 0.f, 1.f, 0.f); }

// lo covers lower (earlier) indices; carry flows high->low: result = f_lo(f_hi(c))
__device__ __forceinline__ float4 comp4(float4 lo, float4 hi) {
    float4 o;
    o.x = lo.x * hi.x;
    o.y = lo.y + lo.x * hi.y;
    o.z = lo.z * hi.z;
    o.w = lo.w + lo.z * hi.w;
    return o;
}

__device__ __forceinline__ float4 shfl_down4(float4 v, int d) {
    float4 o;
    o.x = __shfl_down_sync(0xffffffffu, v.x, d);
    o.y = __shfl_down_sync(0xffffffffu, v.y, d);
    o.z = __shfl_down_sync(0xffffffffu, v.z, d);
    o.w = __shfl_down_sync(0xffffffffu, v.w, d);
    return o;
}

// Inclusive SUFFIX scan within a warp; ALL 32 lanes execute.
__device__ __forceinline__ float4 warp_suffix_scan(float4 v, int lane) {
#pragma unroll
    for (int d = 1; d < 32; d <<= 1) {
        float4 o = shfl_down4(v, d);
        if (lane + d < 32) v = comp4(v, o);
    }
    return v;
}

__device__ __forceinline__ float4 crosswarp_suffix_scan(float4 v, int lane, int n) {
#pragma unroll
    for (int d = 1; d < 32; d <<= 1) {
        if (d >= n) break;
        float4 o = shfl_down4(v, d);
        if (lane + d < n) v = comp4(v, o);
    }
    return v;
}

__device__ __forceinline__ float a1_of(unsigned int bits, int i) {
    return ((bits >> i) & 1u) ? GAMMA : 0.f;
}

// Tile summary from (rr, vv, bits): forward composition (F = f_0 o f_1 o ...)
__device__ __forceinline__ float4 tile_summary_rv(const float* rr, const float* vv,
                                                  unsigned int bits, int nvalid) {
    float av = 1.f, bv = 0.f, aa = 1.f, ba = 0.f;
#pragma unroll
    for (int i = 0; i < ITEMS; i++) {
        if (i < nvalid) {
            float a1 = a1_of(bits, i);
            float delta = rr[i] + a1 * vv[i + 1] - vv[i];
            float a2 = a1 * TAUF;
            bv = bv + av * rr[i]; av = av * a1;
            ba = ba + aa * delta; aa = aa * a2;
        }
    }
    return make_float4(av, bv, aa, ba);
}

// ---------------- Pass 1: summaries + moments + bits; last block fuses carry scan + stats ----------------
__global__ void __launch_bounds__(THREADS) k_pass1(const float* __restrict__ r,
                                                   const float* __restrict__ v,
                                                   const int* __restrict__ m,
                                                   long B, int NB) {
    __shared__ float4 WAGG[NWARPS];
    __shared__ float2 WC[NWARPS];
    __shared__ float SS0[NWARPS], SS1[NWARPS], SS2[NWARPS], SS3[NWARPS], SS4[NWARPS];
    __shared__ int LASTF;
    __shared__ double DS[NWARPS], DQ[NWARPS];
    int t = threadIdx.x, lane = t & 31, w = t >> 5;
    long s = (long)blockIdx.x * CHUNK + (long)t * ITEMS;

    float rr[ITEMS], vv[ITEMS + 1];
    unsigned int bits = 0;
    long rem = B - s;
    int nvalid = (rem >= ITEMS) ? ITEMS : (rem > 0 ? (int)rem : 0);
    if (nvalid == ITEMS) {
        float4 x = *reinterpret_cast<const float4*>(r + s);
        float4 y = *reinterpret_cast<const float4*>(v + s);
        int4  mi = *reinterpret_cast<const int4*>(m + s);
        rr[0] = x.x; rr[1] = x.y; rr[2] = x.z; rr[3] = x.w;
        vv[0] = y.x; vv[1] = y.y; vv[2] = y.z; vv[3] = y.w;
        bits = (unsigned int)(mi.x & 1) | ((unsigned int)(mi.y & 1) << 1)
             | ((unsigned int)(mi.z & 1) << 2) | ((unsigned int)(mi.w & 1) << 3);
        vv[ITEMS] = (s + ITEMS < B) ? v[s + ITEMS] : 0.f;
    } else {
#pragma unroll
        for (int i = 0; i < ITEMS; i++) {
            if (i < nvalid) {
                rr[i] = r[s + i];
                vv[i] = v[s + i];
                bits |= (unsigned int)(m[s + i] & 1) << i;
            } else { rr[i] = 0.f; vv[i] = 0.f; }
        }
        vv[ITEMS] = 0.f;
    }
    g_bits[blockIdx.x * THREADS + t] = (unsigned char)bits;

    float4 f = tile_summary_rv(rr, vv, bits, nvalid);
    float4 sfx = warp_suffix_scan(f, lane);
    if (lane == 0) WAGG[w] = sfx;
    __syncthreads();
    if (w == 0) {                               // whole warp 0
        float4 sw = (lane < NWARPS) ? WAGG[lane] : ident4();
        sw = crosswarp_suffix_scan(sw, lane, NWARPS);
        if (lane == 0) g_blk[blockIdx.x] = sw;
        float4 ex = shfl_down4(sw, 1);
        if (lane >= NWARPS - 1) ex = ident4();
        if (lane < NWARPS) WC[lane] = make_float2(ex.w, ex.z);   // (Pa, Ga) of warp
    }
    __syncthreads();
    float2 wc = WC[w];
    float4 X = shfl_down4(sfx, 1);
    if (lane == 31) X = ident4();
    float P = X.w + X.z * wc.x;
    float G = X.z * wc.y;
    float sp = 0.f, sg = 0.f, spp = 0.f, spg = 0.f, sgg = 0.f;
#pragma unroll
    for (int i = ITEMS - 1; i >= 0; i--) {
        if (i < nvalid) {
            float a1 = a1_of(bits, i);
            float delta = rr[i] + a1 * vv[i + 1] - vv[i];
            float a2 = a1 * TAUF;
            P = delta + a2 * P;
            G = a2 * G;
            sp += P; sg += G;
            spp += P * P; spg += P * G; sgg += G * G;
        }
    }
#pragma unroll
    for (int d = 16; d > 0; d >>= 1) {
        sp  += __shfl_down_sync(0xffffffffu, sp, d);
        sg  += __shfl_down_sync(0xffffffffu, sg, d);
        spp += __shfl_down_sync(0xffffffffu, spp, d);
        spg += __shfl_down_sync(0xffffffffu, spg, d);
        sgg += __shfl_down_sync(0xffffffffu, sgg, d);
    }
    if (lane == 0) { SS0[w] = sp; SS1[w] = sg; SS2[w] = spp; SS3[w] = spg; SS4[w] = sgg; }
    __syncthreads();
    if (w == 0) {
        bool ok = lane < NWARPS;
        float a0 = ok ? SS0[lane] : 0.f;
        float a1 = ok ? SS1[lane] : 0.f;
        float a2 = ok ? SS2[lane] : 0.f;
        float a3 = ok ? SS3[lane] : 0.f;
        float a4 = ok ? SS4[lane] : 0.f;
#pragma unroll
        for (int d = NWARPS / 2; d > 0; d >>= 1) {
            a0 += __shfl_down_sync(0xffffffffu, a0, d);
            a1 += __shfl_down_sync(0xffffffffu, a1, d);
            a2 += __shfl_down_sync(0xffffffffu, a2, d);
            a3 += __shfl_down_sync(0xffffffffu, a3, d);
            a4 += __shfl_down_sync(0xffffffffu, a4, d);
        }
        if (lane == 0) {
            g_mA[blockIdx.x] = make_float4(a0, a1, a2, a3);
            g_mB[blockIdx.x] = a4;
        }
    }

    // allow pass3 to launch early (PDL); it only reads our outputs after gridDepSync
#if __CUDA_ARCH__ >= 900
    cudaTriggerProgrammaticLaunchCompletion();
#endif

    // ---- last-done block performs the (former) pass2 inline ----
    if (t == 0) {
        __threadfence();
        unsigned int dn = atomicAdd(&g_done, 1);
        LASTF = (dn == (unsigned int)NB - 1) ? 1 : 0;
    }
    __syncthreads();
    if (!LASTF) return;
    __threadfence();                            // all other blocks' writes visible

    int base = t * PER;
    float4 E = ident4();
#pragma unroll 1
    for (int i = 0; i < PER; i += 4) {          // batch 4 loads for MLP
        int b = base + i;
        float4 f0 = (b + 0 < NB) ? g_blk[b + 0] : ident4();
        float4 f1 = (b + 1 < NB) ? g_blk[b + 1] : ident4();
        float4 f2 = (b + 2 < NB) ? g_blk[b + 2] : ident4();
        float4 f3 = (b + 3 < NB) ? g_blk[b + 3] : ident4();
        E = comp4(comp4(comp4(comp4(E, f0), f1), f2), f3);
    }
    float4 sfx2 = warp_suffix_scan(E, lane);
    if (lane == 0) WAGG[w] = sfx2;
    __syncthreads();
    if (w == 0) {
        float4 sw = (lane < NWARPS) ? WAGG[lane] : ident4();
        sw = crosswarp_suffix_scan(sw, lane, NWARPS);
        float4 ex = shfl_down4(sw, 1);
        if (lane >= NWARPS - 1) ex = ident4();
        if (lane < NWARPS) WC[lane] = make_float2(ex.y, ex.w);   // VALUE carries (c=0)
    }
    __syncthreads();
    float2 wcar = WC[w];
    float4 X2 = shfl_down4(sfx2, 1);
    if (lane == 31) X2 = ident4();
    float2 V;                                   // carry entering block base+PER-1
    V.x = X2.y + X2.x * wcar.x;
    V.y = X2.w + X2.z * wcar.y;
    double dsum = 0.0, dssq = 0.0;
#pragma unroll 1
    for (int i = PER - 1; i >= 0; i -= 4) {     // batch payload loads for MLP
        int b3 = base + i;
        float4 mA0[4]; float mB0[4]; float4 fb0[4];
#pragma unroll
        for (int k = 0; k < 4; k++) {
            int b = b3 - 3 + k;
            bool ok = (b >= 0) && (b < NB);
            mA0[k] = ok ? g_mA[b] : make_float4(0.f, 0.f, 0.f, 0.f);
            mB0[k] = ok ? g_mB[b] : 0.f;
            fb0[k] = ok ? g_blk[b] : ident4();
        }
#pragma unroll
        for (int k = 3; k >= 0; k--) {
            int b = b3 - 3 + k;
            if (b >= 0 && b < NB) {
                g_carry[b] = V;
                float c = V.y;
                dsum += (double)(mA0[k].x + mA0[k].y * c);
                dssq += (double)(mA0[k].z + 2.f * mA0[k].w * c + mB0[k] * c * c);
                float2 nV;
                nV.x = fb0[k].y + fb0[k].x * V.x;
                nV.y = fb0[k].w + fb0[k].z * V.y;
                V = nV;
            }
        }
    }
#pragma unroll
    for (int d = 16; d > 0; d >>= 1) {
        dsum += __shfl_down_sync(0xffffffffu, dsum, d);
        dssq += __shfl_down_sync(0xffffffffu, dssq, d);
    }
    if (lane == 0) { DS[w] = dsum; DQ[w] = dssq; }
    __syncthreads();
    if (w == 0) {
        bool ok = lane < NWARPS;
        double sd = ok ? DS[lane] : 0.0;
        double qd = ok ? DQ[lane] : 0.0;
#pragma unroll
        for (int d = NWARPS / 2; d > 0; d >>= 1) {
            sd += __shfl_down_sync(0xffffffffu, sd, d);
            qd += __shfl_down_sync(0xffffffffu, qd, d);
        }
        if (lane == 0) {
            double mean = sd / (double)B;
            double var  = (qd - sd * mean) / (double)(B - 1);
            g_normc = make_float2((float)mean, (float)(1.0 / sqrt(var)));
            g_done = 0;                         // reset for next graph replay
        }
    }
}

// ---------------- Pass 3 (PDL): preload inputs, sync, fixup + normalized stores ----------------
__global__ void __launch_bounds__(THREADS) k_pass3(const float* __restrict__ r,
                                                   const float* __restrict__ v,
                                                   float* __restrict__ outA,
                                                   float* __restrict__ outVT, long B) {
    __shared__ float4 WAGG[NWARPS];
    __shared__ float2 WCARRY[NWARPS];
    int t = threadIdx.x, lane = t & 31, w = t >> 5;
    long s = (long)blockIdx.x * CHUNK + (long)t * ITEMS;

    // ---- pre-sync: load pure inputs (independent of pass1) ----
    float rr[ITEMS], vv[ITEMS + 1];
    long rem = B - s;
    int nvalid = (rem >= ITEMS) ? ITEMS : (rem > 0 ? (int)rem : 0);
    if (nvalid == ITEMS) {
        float4 x = *reinterpret_cast<const float4*>(r + s);
        float4 y = *reinterpret_cast<const float4*>(v + s);
        rr[0] = x.x; rr[1] = x.y; rr[2] = x.z; rr[3] = x.w;
        vv[0] = y.x; vv[1] = y.y; vv[2] = y.z; vv[3] = y.w;
        vv[ITEMS] = (s + ITEMS < B) ? v[s + ITEMS] : 0.f;
    } else {
#pragma unroll
        for (int i = 0; i < ITEMS; i++) {
            if (i < nvalid) { rr[i] = r[s + i]; vv[i] = v[s + i]; }
            else { rr[i] = 0.f; vv[i] = 0.f; }
        }
        vv[ITEMS] = 0.f;
    }

    // ---- wait for pass1 completion before reading its outputs ----
#if __CUDA_ARCH__ >= 900
    cudaGridDependencySynchronize();
#endif

    unsigned int bits = g_bits[blockIdx.x * THREADS + t];
    float2 nc = g_normc;
    float4 f = tile_summary_rv(rr, vv, bits, nvalid);
    float4 sfx = warp_suffix_scan(f, lane);
    if (lane == 0) WAGG[w] = sfx;
    __syncthreads();
    if (w == 0) {
        float4 sw = (lane < NWARPS) ? WAGG[lane] : ident4();
        sw = crosswarp_suffix_scan(sw, lane, NWARPS);
        float4 ex = shfl_down4(sw, 1);
        if (lane >= NWARPS - 1) ex = ident4();
        float2 cb = g_carry[blockIdx.x];
        float2 wcv;
        wcv.x = ex.y + ex.x * cb.x;
        wcv.y = ex.w + ex.z * cb.y;
        if (lane < NWARPS) WCARRY[lane] = wcv;
    }
    __syncthreads();
    float2 wcar = WCARRY[w];
    float4 X = shfl_down4(sfx, 1);
    if (lane == 31) X = ident4();
    float cvt = X.y + X.x * wcar.x;
    float ca  = X.w + X.z * wcar.y;

    float mean = nc.x, istd = nc.y;
    // fixup: vt -> rr[i], A -> vv[i+1] (vv[i+1] dead after delta_i)
#pragma unroll
    for (int i = ITEMS - 1; i >= 0; i--) {
        if (i < nvalid) {
            float a1 = a1_of(bits, i);
            float delta = rr[i] + a1 * vv[i + 1] - vv[i];
            float vt = rr[i] + a1 * cvt;
            float A  = delta + a1 * TAUF * ca;
            rr[i] = vt;
            vv[i + 1] = A;
            cvt = vt; ca = A;
        }
    }
    if (nvalid == ITEMS) {
        *reinterpret_cast<float4*>(outVT + s) = make_float4(rr[0], rr[1], rr[2], rr[3]);
        *reinterpret_cast<float4*>(outA + s) =
            make_float4((vv[1] - mean) * istd, (vv[2] - mean) * istd,
                        (vv[3] - mean) * istd, (vv[4] - mean) * istd);
    } else {
#pragma unroll
        for (int i = 0; i < ITEMS; i++) {
            if (i < nvalid) {
                outVT[s + i] = rr[i];
                outA[s + i]  = (vv[i + 1] - mean) * istd;
            }
        }
    }
}

extern "C" void kernel_launch(void* const* d_in, const int* in_sizes, int n_in,
                              void* d_out, int out_size) {
    const float* r = (const float*)d_in[0];
    const float* v = (const float*)d_in[1];
    const int*   m = (const int*)d_in[2];
    long B = (long)in_sizes[0];
    float* outA  = (float*)d_out;
    float* outVT = outA + B;

    int NB = (int)((B + CHUNK - 1) / CHUNK);
    if (NB > NB_MAX) NB = NB_MAX;   // this problem: B=4194304 -> NB=4096

    k_pass1<<<NB, THREADS>>>(r, v, m, B, NB);

    // PDL launch: pass3 may start while pass1 drains; it gridDepSyncs before
    // reading pass1's outputs. Degrades to a normal serialized launch if PDL
    // is unavailable.
    cudaLaunchConfig_t cfg = {};
    cfg.gridDim = dim3((unsigned)NB, 1, 1);
    cfg.blockDim = dim3(THREADS, 1, 1);
    cfg.dynamicSmemBytes = 0;
    cfg.stream = 0;
    cudaLaunchAttribute attrs[1];
    attrs[0].id = cudaLaunchAttributeProgrammaticStreamSerialization;
    attrs[0].val.programmaticStreamSerializationAllowed = 1;
    cfg.attrs = attrs;
    cfg.numAttrs = 1;
    cudaLaunchKernelEx(&cfg, k_pass3, r, v, outA, outVT, B);
}

// round 13
// speedup vs baseline: 1.2538x; 1.2538x over previous
#include <cuda_runtime.h>
#include <math.h>

#define GAMMA 0.99f
#define TAUF  0.95f

constexpr int THREADS = 256;
constexpr int ITEMS   = 8;
constexpr int CHUNK   = THREADS * ITEMS;   // 2048
constexpr int NWARPS  = THREADS / 32;      // 8
constexpr int PER     = 8;                 // summaries per thread in fused pass2
constexpr int NB_MAX  = THREADS * PER;     // 2048 blocks max (B <= 4,194,304)

// Scratch (device globals; no allocation allowed)
__device__ float4 g_blk[NB_MAX];     // per-block affine summary: (a_vt, b_vt, a_A, b_A)
__device__ float2 g_carry[NB_MAX];   // per-block incoming carry VALUES (vt, A)
__device__ float4 g_mA[NB_MAX];      // per-block (SP, SG, SPP, SPG)
__device__ float  g_mB[NB_MAX];      // per-block SGG
__device__ unsigned char g_bits[NB_MAX * THREADS];  // packed masks, 1 byte per thread-tile
__device__ float2 g_normc;           // (mean, inv_std)
__device__ unsigned int g_done = 0;  // finish counter (reset by last block)

__device__ __forceinline__ float4 ident4() { return make_float4(1.f, 0.f, 1.f, 0.f); }

// lo covers lower (earlier) indices; carry flows high->low: result = f_lo(f_hi(c))
__device__ __forceinline__ float4 comp4(float4 lo, float4 hi) {
    float4 o;
    o.x = lo.x * hi.x;
    o.y = lo.y + lo.x * hi.y;
    o.z = lo.z * hi.z;
    o.w = lo.w + lo.z * hi.w;
    return o;
}

__device__ __forceinline__ float4 shfl_down4(float4 v, int d) {
    float4 o;
    o.x = __shfl_down_sync(0xffffffffu, v.x, d);
    o.y = __shfl_down_sync(0xffffffffu, v.y, d);
    o.z = __shfl_down_sync(0xffffffffu, v.z, d);
    o.w = __shfl_down_sync(0xffffffffu, v.w, d);
    return o;
}

// Inclusive SUFFIX scan within a warp; ALL 32 lanes execute.
__device__ __forceinline__ float4 warp_suffix_scan(float4 v, int lane) {
#pragma unroll
    for (int d = 1; d < 32; d <<= 1) {
        float4 o = shfl_down4(v, d);
        if (lane + d < 32) v = comp4(v, o);
    }
    return v;
}

__device__ __forceinline__ float4 crosswarp_suffix_scan(float4 v, int lane, int n) {
#pragma unroll
    for (int d = 1; d < 32; d <<= 1) {
        if (d >= n) break;
        float4 o = shfl_down4(v, d);
        if (lane + d < n) v = comp4(v, o);
    }
    return v;
}

__device__ __forceinline__ float a1_of(unsigned int bits, int i) {
    return ((bits >> i) & 1u) ? GAMMA : 0.f;
}

// Tile summary from (rr, vv, bits): forward composition (F = f_0 o f_1 o ...)
__device__ __forceinline__ float4 tile_summary_rv(const float* rr, const float* vv,
                                                  unsigned int bits, int nvalid) {
    float av = 1.f, bv = 0.f, aa = 1.f, ba = 0.f;
#pragma unroll
    for (int i = 0; i < ITEMS; i++) {
        if (i < nvalid) {
            float a1 = a1_of(bits, i);
            float delta = rr[i] + a1 * vv[i + 1] - vv[i];
            float a2 = a1 * TAUF;
            bv = bv + av * rr[i]; av = av * a1;
            ba = ba + aa * delta; aa = aa * a2;
        }
    }
    return make_float4(av, bv, aa, ba);
}

// ---------------- Pass 1: summaries + moments + bits; last block fuses carry scan + stats ----------------
__global__ void __launch_bounds__(THREADS) k_pass1(const float* __restrict__ r,
                                                   const float* __restrict__ v,
                                                   const int* __restrict__ m,
                                                   long B, int NB) {
    __shared__ float4 WAGG[NWARPS];
    __shared__ float2 WC[NWARPS];
    __shared__ float SS0[NWARPS], SS1[NWARPS], SS2[NWARPS], SS3[NWARPS], SS4[NWARPS];
    __shared__ int LASTF;
    __shared__ double DS[NWARPS], DQ[NWARPS];
    int t = threadIdx.x, lane = t & 31, w = t >> 5;
    long s = (long)blockIdx.x * CHUNK + (long)t * ITEMS;

    float rr[ITEMS], vv[ITEMS + 1];
    unsigned int bits = 0;
    long rem = B - s;
    int nvalid = (rem >= ITEMS) ? ITEMS : (rem > 0 ? (int)rem : 0);
    if (nvalid == ITEMS) {
#pragma unroll
        for (int j = 0; j < ITEMS / 4; j++) {
            float4 x = *reinterpret_cast<const float4*>(r + s + 4 * j);
            float4 y = *reinterpret_cast<const float4*>(v + s + 4 * j);
            int4  mi = *reinterpret_cast<const int4*>(m + s + 4 * j);
            rr[4*j+0] = x.x; rr[4*j+1] = x.y; rr[4*j+2] = x.z; rr[4*j+3] = x.w;
            vv[4*j+0] = y.x; vv[4*j+1] = y.y; vv[4*j+2] = y.z; vv[4*j+3] = y.w;
            bits |= (unsigned int)(mi.x & 1) << (4*j+0);
            bits |= (unsigned int)(mi.y & 1) << (4*j+1);
            bits |= (unsigned int)(mi.z & 1) << (4*j+2);
            bits |= (unsigned int)(mi.w & 1) << (4*j+3);
        }
        vv[ITEMS] = (s + ITEMS < B) ? v[s + ITEMS] : 0.f;
    } else {
#pragma unroll
        for (int i = 0; i < ITEMS; i++) {
            if (i < nvalid) {
                rr[i] = r[s + i];
                vv[i] = v[s + i];
                bits |= (unsigned int)(m[s + i] & 1) << i;
            } else { rr[i] = 0.f; vv[i] = 0.f; }
        }
        vv[ITEMS] = 0.f;
    }
    g_bits[blockIdx.x * THREADS + t] = (unsigned char)bits;

    float4 f = tile_summary_rv(rr, vv, bits, nvalid);
    float4 sfx = warp_suffix_scan(f, lane);
    if (lane == 0) WAGG[w] = sfx;
    __syncthreads();
    if (w == 0) {                               // whole warp 0
        float4 sw = (lane < NWARPS) ? WAGG[lane] : ident4();
        sw = crosswarp_suffix_scan(sw, lane, NWARPS);
        if (lane == 0) g_blk[blockIdx.x] = sw;
        float4 ex = shfl_down4(sw, 1);
        if (lane >= NWARPS - 1) ex = ident4();
        if (lane < NWARPS) WC[lane] = make_float2(ex.w, ex.z);   // (Pa, Ga) of warp
    }
    __syncthreads();
    float2 wc = WC[w];
    float4 X = shfl_down4(sfx, 1);
    if (lane == 31) X = ident4();
    float P = X.w + X.z * wc.x;
    float G = X.z * wc.y;
    float sp = 0.f, sg = 0.f, spp = 0.f, spg = 0.f, sgg = 0.f;
#pragma unroll
    for (int i = ITEMS - 1; i >= 0; i--) {
        if (i < nvalid) {
            float a1 = a1_of(bits, i);
            float delta = rr[i] + a1 * vv[i + 1] - vv[i];
            float a2 = a1 * TAUF;
            P = delta + a2 * P;
            G = a2 * G;
            sp += P; sg += G;
            spp += P * P; spg += P * G; sgg += G * G;
        }
    }
#pragma unroll
    for (int d = 16; d > 0; d >>= 1) {
        sp  += __shfl_down_sync(0xffffffffu, sp, d);
        sg  += __shfl_down_sync(0xffffffffu, sg, d);
        spp += __shfl_down_sync(0xffffffffu, spp, d);
        spg += __shfl_down_sync(0xffffffffu, spg, d);
        sgg += __shfl_down_sync(0xffffffffu, sgg, d);
    }
    if (lane == 0) { SS0[w] = sp; SS1[w] = sg; SS2[w] = spp; SS3[w] = spg; SS4[w] = sgg; }
    __syncthreads();
    if (w == 0) {
        bool ok = lane < NWARPS;
        float a0 = ok ? SS0[lane] : 0.f;
        float a1 = ok ? SS1[lane] : 0.f;
        float a2 = ok ? SS2[lane] : 0.f;
        float a3 = ok ? SS3[lane] : 0.f;
        float a4 = ok ? SS4[lane] : 0.f;
#pragma unroll
        for (int d = NWARPS / 2; d > 0; d >>= 1) {
            a0 += __shfl_down_sync(0xffffffffu, a0, d);
            a1 += __shfl_down_sync(0xffffffffu, a1, d);
            a2 += __shfl_down_sync(0xffffffffu, a2, d);
            a3 += __shfl_down_sync(0xffffffffu, a3, d);
            a4 += __shfl_down_sync(0xffffffffu, a4, d);
        }
        if (lane == 0) {
            g_mA[blockIdx.x] = make_float4(a0, a1, a2, a3);
            g_mB[blockIdx.x] = a4;
        }
    }

    // allow pass3 to launch (its blocks wait idle at gridDepSync; no traffic contention)
#if __CUDA_ARCH__ >= 900
    cudaTriggerProgrammaticLaunchCompletion();
#endif

    // ---- last-done block performs the (former) pass2 inline ----
    if (t == 0) {
        __threadfence();
        unsigned int dn = atomicAdd(&g_done, 1);
        LASTF = (dn == (unsigned int)NB - 1) ? 1 : 0;
    }
    __syncthreads();
    if (!LASTF) return;
    __threadfence();                            // all other blocks' writes visible

    int base = t * PER;
    float4 E = ident4();
#pragma unroll 1
    for (int i = 0; i < PER; i += 4) {          // batch loads for MLP
        int b = base + i;
        float4 f0 = (b + 0 < NB) ? g_blk[b + 0] : ident4();
        float4 f1 = (b + 1 < NB) ? g_blk[b + 1] : ident4();
        float4 f2 = (b + 2 < NB) ? g_blk[b + 2] : ident4();
        float4 f3 = (b + 3 < NB) ? g_blk[b + 3] : ident4();
        E = comp4(comp4(comp4(comp4(E, f0), f1), f2), f3);
    }
    float4 sfx2 = warp_suffix_scan(E, lane);
    if (lane == 0) WAGG[w] = sfx2;
    __syncthreads();
    if (w == 0) {
        float4 sw = (lane < NWARPS) ? WAGG[lane] : ident4();
        sw = crosswarp_suffix_scan(sw, lane, NWARPS);
        float4 ex = shfl_down4(sw, 1);
        if (lane >= NWARPS - 1) ex = ident4();
        if (lane < NWARPS) WC[lane] = make_float2(ex.y, ex.w);   // VALUE carries (c=0)
    }
    __syncthreads();
    float2 wcar = WC[w];
    float4 X2 = shfl_down4(sfx2, 1);
    if (lane == 31) X2 = ident4();
    float2 V;                                   // carry entering block base+PER-1
    V.x = X2.y + X2.x * wcar.x;
    V.y = X2.w + X2.z * wcar.y;
    double dsum = 0.0, dssq = 0.0;
#pragma unroll 1
    for (int i = PER - 1; i >= 0; i -= 4) {     // batch payload loads for MLP
        int b3 = base + i;
        float4 mA0[4]; float mB0[4]; float4 fb0[4];
#pragma unroll
        for (int k = 0; k < 4; k++) {
            int b = b3 - 3 + k;
            bool ok = (b >= 0) && (b < NB);
            mA0[k] = ok ? g_mA[b] : make_float4(0.f, 0.f, 0.f, 0.f);
            mB0[k] = ok ? g_mB[b] : 0.f;
            fb0[k] = ok ? g_blk[b] : ident4();
        }
#pragma unroll
        for (int k = 3; k >= 0; k--) {
            int b = b3 - 3 + k;
            if (b >= 0 && b < NB) {
                g_carry[b] = V;
                float c = V.y;
                dsum += (double)(mA0[k].x + mA0[k].y * c);
                dssq += (double)(mA0[k].z + 2.f * mA0[k].w * c + mB0[k] * c * c);
                float2 nV;
                nV.x = fb0[k].y + fb0[k].x * V.x;
                nV.y = fb0[k].w + fb0[k].z * V.y;
                V = nV;
            }
        }
    }
#pragma unroll
    for (int d = 16; d > 0; d >>= 1) {
        dsum += __shfl_down_sync(0xffffffffu, dsum, d);
        dssq += __shfl_down_sync(0xffffffffu, dssq, d);
    }
    if (lane == 0) { DS[w] = dsum; DQ[w] = dssq; }
    __syncthreads();
    if (w == 0) {
        bool ok = lane < NWARPS;
        double sd = ok ? DS[lane] : 0.0;
        double qd = ok ? DQ[lane] : 0.0;
#pragma unroll
        for (int d = NWARPS / 2; d > 0; d >>= 1) {
            sd += __shfl_down_sync(0xffffffffu, sd, d);
            qd += __shfl_down_sync(0xffffffffu, qd, d);
        }
        if (lane == 0) {
            double mean = sd / (double)B;
            double var  = (qd - sd * mean) / (double)(B - 1);
            g_normc = make_float2((float)mean, (float)(1.0 / sqrt(var)));
            g_done = 0;                         // reset for next graph replay
        }
    }
}

// ---------------- Pass 3: sync FIRST (no preload), then fixup + streaming stores ----------------
__global__ void __launch_bounds__(THREADS, 5) k_pass3(const float* __restrict__ r,
                                                      const float* __restrict__ v,
                                                      float* __restrict__ outA,
                                                      float* __restrict__ outVT, long B) {
    // wait for pass1 BEFORE issuing any memory traffic (no bandwidth contention)
#if __CUDA_ARCH__ >= 900
    cudaGridDependencySynchronize();
#endif
    __shared__ float4 WAGG[NWARPS];
    __shared__ float2 WCARRY[NWARPS];
    int t = threadIdx.x, lane = t & 31, w = t >> 5;
    long s = (long)blockIdx.x * CHUNK + (long)t * ITEMS;

    float rr[ITEMS], vv[ITEMS + 1];
    unsigned int bits = g_bits[blockIdx.x * THREADS + t];
    long rem = B - s;
    int nvalid = (rem >= ITEMS) ? ITEMS : (rem > 0 ? (int)rem : 0);
    if (nvalid == ITEMS) {
#pragma unroll
        for (int j = 0; j < ITEMS / 4; j++) {
            float4 x = *reinterpret_cast<const float4*>(r + s + 4 * j);
            float4 y = *reinterpret_cast<const float4*>(v + s + 4 * j);
            rr[4*j+0] = x.x; rr[4*j+1] = x.y; rr[4*j+2] = x.z; rr[4*j+3] = x.w;
            vv[4*j+0] = y.x; vv[4*j+1] = y.y; vv[4*j+2] = y.z; vv[4*j+3] = y.w;
        }
        vv[ITEMS] = (s + ITEMS < B) ? v[s + ITEMS] : 0.f;
    } else {
#pragma unroll
        for (int i = 0; i < ITEMS; i++) {
            if (i < nvalid) { rr[i] = r[s + i]; vv[i] = v[s + i]; }
            else { rr[i] = 0.f; vv[i] = 0.f; }
        }
        vv[ITEMS] = 0.f;
    }

    float2 nc = g_normc;
    float4 f = tile_summary_rv(rr, vv, bits, nvalid);
    float4 sfx = warp_suffix_scan(f, lane);
    if (lane == 0) WAGG[w] = sfx;
    __syncthreads();
    if (w == 0) {
        float4 sw = (lane < NWARPS) ? WAGG[lane] : ident4();
        sw = crosswarp_suffix_scan(sw, lane, NWARPS);
        float4 ex = shfl_down4(sw, 1);
        if (lane >= NWARPS - 1) ex = ident4();
        float2 cb = g_carry[blockIdx.x];
        float2 wcv;
        wcv.x = ex.y + ex.x * cb.x;
        wcv.y = ex.w + ex.z * cb.y;
        if (lane < NWARPS) WCARRY[lane] = wcv;
    }
    __syncthreads();
    float2 wcar = WCARRY[w];
    float4 X = shfl_down4(sfx, 1);
    if (lane == 31) X = ident4();
    float cvt = X.y + X.x * wcar.x;
    float ca  = X.w + X.z * wcar.y;

    float mean = nc.x, istd = nc.y;
    // fixup: vt -> rr[i], A -> vv[i+1] (vv[i+1] dead after delta_i)
#pragma unroll
    for (int i = ITEMS - 1; i >= 0; i--) {
        if (i < nvalid) {
            float a1 = a1_of(bits, i);
            float delta = rr[i] + a1 * vv[i + 1] - vv[i];
            float vt = rr[i] + a1 * cvt;
            float A  = delta + a1 * TAUF * ca;
            rr[i] = vt;
            vv[i + 1] = A;
            cvt = vt; ca = A;
        }
    }
    if (nvalid == ITEMS) {
        // streaming stores: outputs are never re-read; keep L2 for input reuse
        __stcs(reinterpret_cast<float4*>(outVT + s), make_float4(rr[0], rr[1], rr[2], rr[3]));
        __stcs(reinterpret_cast<float4*>(outVT + s + 4), make_float4(rr[4], rr[5], rr[6], rr[7]));
        __stcs(reinterpret_cast<float4*>(outA + s),
               make_float4((vv[1] - mean) * istd, (vv[2] - mean) * istd,
                           (vv[3] - mean) * istd, (vv[4] - mean) * istd));
        __stcs(reinterpret_cast<float4*>(outA + s + 4),
               make_float4((vv[5] - mean) * istd, (vv[6] - mean) * istd,
                           (vv[7] - mean) * istd, (vv[8] - mean) * istd));
    } else {
#pragma unroll
        for (int i = 0; i < ITEMS; i++) {
            if (i < nvalid) {
                outVT[s + i] = rr[i];
                outA[s + i]  = (vv[i + 1] - mean) * istd;
            }
        }
    }
}

extern "C" void kernel_launch(void* const* d_in, const int* in_sizes, int n_in,
                              void* d_out, int out_size) {
    const float* r = (const float*)d_in[0];
    const float* v = (const float*)d_in[1];
    const int*   m = (const int*)d_in[2];
    long B = (long)in_sizes[0];
    float* outA  = (float*)d_out;
    float* outVT = outA + B;

    int NB = (int)((B + CHUNK - 1) / CHUNK);
    if (NB > NB_MAX) NB = NB_MAX;   // this problem: B=4194304 -> NB=2048

    k_pass1<<<NB, THREADS>>>(r, v, m, B, NB);

    // PDL launch: pass3 blocks start early but gridDepSync FIRST (idle wait, no
    // traffic contention). Hides launch/drain gap only.
    cudaLaunchConfig_t cfg = {};
    cfg.gridDim = dim3((unsigned)NB, 1, 1);
    cfg.blockDim = dim3(THREADS, 1, 1);
    cfg.dynamicSmemBytes = 0;
    cfg.stream = 0;
    cudaLaunchAttribute attrs[1];
    attrs[0].id = cudaLaunchAttributeProgrammaticStreamSerialization;
    attrs[0].val.programmaticStreamSerializationAllowed = 1;
    cfg.attrs = attrs;
    cfg.numAttrs = 1;
    cudaLaunchKernelEx(&cfg, k_pass3, r, v, outA, outVT, B);
}

// round 14
// speedup vs baseline: 1.2745x; 1.0165x over previous
#include <cuda_runtime.h>
#include <math.h>

#define GAMMA 0.99f
#define TAUF  0.95f

constexpr int THREADS = 256;
constexpr int ITEMS   = 8;
constexpr int CHUNK   = THREADS * ITEMS;   // 2048
constexpr int NWARPS  = THREADS / 32;      // 8
constexpr int PER     = 8;                 // summaries per thread in fused pass2
constexpr int NB_MAX  = THREADS * PER;     // 2048 blocks max (B <= 4,194,304)

// Scratch (device globals; no allocation allowed)
__device__ float4 g_blk[NB_MAX];     // per-block affine summary: (a_vt, b_vt, a_A, b_A)
__device__ float2 g_carry[NB_MAX];   // per-block incoming carry VALUES (vt, A)
__device__ float4 g_mA[NB_MAX];      // per-block (SP, SG, SPP, SPG)
__device__ float  g_mB[NB_MAX];      // per-block SGG
__device__ unsigned char g_bits[NB_MAX * THREADS];  // packed masks, 1 byte per thread-tile
__device__ float4 g_tc[NB_MAX * THREADS];  // per-thread carry coeffs (Pvt, Gvt, PA, GA)
__device__ float2 g_normc;           // (mean, inv_std)
__device__ unsigned int g_done = 0;  // finish counter (reset by last block)

__device__ __forceinline__ float4 ident4() { return make_float4(1.f, 0.f, 1.f, 0.f); }

// lo covers lower (earlier) indices; carry flows high->low: result = f_lo(f_hi(c))
__device__ __forceinline__ float4 comp4(float4 lo, float4 hi) {
    float4 o;
    o.x = lo.x * hi.x;
    o.y = lo.y + lo.x * hi.y;
    o.z = lo.z * hi.z;
    o.w = lo.w + lo.z * hi.w;
    return o;
}

__device__ __forceinline__ float4 shfl_down4(float4 v, int d) {
    float4 o;
    o.x = __shfl_down_sync(0xffffffffu, v.x, d);
    o.y = __shfl_down_sync(0xffffffffu, v.y, d);
    o.z = __shfl_down_sync(0xffffffffu, v.z, d);
    o.w = __shfl_down_sync(0xffffffffu, v.w, d);
    return o;
}

// Inclusive SUFFIX scan within a warp; ALL 32 lanes execute.
__device__ __forceinline__ float4 warp_suffix_scan(float4 v, int lane) {
#pragma unroll
    for (int d = 1; d < 32; d <<= 1) {
        float4 o = shfl_down4(v, d);
        if (lane + d < 32) v = comp4(v, o);
    }
    return v;
}

__device__ __forceinline__ float4 crosswarp_suffix_scan(float4 v, int lane, int n) {
#pragma unroll
    for (int d = 1; d < 32; d <<= 1) {
        if (d >= n) break;
        float4 o = shfl_down4(v, d);
        if (lane + d < n) v = comp4(v, o);
    }
    return v;
}

__device__ __forceinline__ float a1_of(unsigned int bits, int i) {
    return ((bits >> i) & 1u) ? GAMMA : 0.f;
}

// Tile summary from (rr, vv, bits): forward composition (F = f_0 o f_1 o ...)
__device__ __forceinline__ float4 tile_summary_rv(const float* rr, const float* vv,
                                                  unsigned int bits, int nvalid) {
    float av = 1.f, bv = 0.f, aa = 1.f, ba = 0.f;
#pragma unroll
    for (int i = 0; i < ITEMS; i++) {
        if (i < nvalid) {
            float a1 = a1_of(bits, i);
            float delta = rr[i] + a1 * vv[i + 1] - vv[i];
            float a2 = a1 * TAUF;
            bv = bv + av * rr[i]; av = av * a1;
            ba = ba + aa * delta; aa = aa * a2;
        }
    }
    return make_float4(av, bv, aa, ba);
}

// ---------------- Pass 1: summaries + per-thread carry coeffs + moments ----------------
__global__ void __launch_bounds__(THREADS) k_pass1(const float* __restrict__ r,
                                                   const float* __restrict__ v,
                                                   const int* __restrict__ m,
                                                   long B, int NB) {
    __shared__ float4 WAGG[NWARPS];
    __shared__ float4 WC[NWARPS];               // (Pvt, Gvt, PA, GA) per warp
    __shared__ float SS0[NWARPS], SS1[NWARPS], SS2[NWARPS], SS3[NWARPS], SS4[NWARPS];
    __shared__ int LASTF;
    __shared__ double DS[NWARPS], DQ[NWARPS];
    int t = threadIdx.x, lane = t & 31, w = t >> 5;
    long s = (long)blockIdx.x * CHUNK + (long)t * ITEMS;

    float rr[ITEMS], vv[ITEMS + 1];
    unsigned int bits = 0;
    long rem = B - s;
    int nvalid = (rem >= ITEMS) ? ITEMS : (rem > 0 ? (int)rem : 0);
    if (nvalid == ITEMS) {
#pragma unroll
        for (int j = 0; j < ITEMS / 4; j++) {
            float4 x = *reinterpret_cast<const float4*>(r + s + 4 * j);
            float4 y = *reinterpret_cast<const float4*>(v + s + 4 * j);
            int4  mi = *reinterpret_cast<const int4*>(m + s + 4 * j);
            rr[4*j+0] = x.x; rr[4*j+1] = x.y; rr[4*j+2] = x.z; rr[4*j+3] = x.w;
            vv[4*j+0] = y.x; vv[4*j+1] = y.y; vv[4*j+2] = y.z; vv[4*j+3] = y.w;
            bits |= (unsigned int)(mi.x & 1) << (4*j+0);
            bits |= (unsigned int)(mi.y & 1) << (4*j+1);
            bits |= (unsigned int)(mi.z & 1) << (4*j+2);
            bits |= (unsigned int)(mi.w & 1) << (4*j+3);
        }
        vv[ITEMS] = (s + ITEMS < B) ? v[s + ITEMS] : 0.f;
    } else {
#pragma unroll
        for (int i = 0; i < ITEMS; i++) {
            if (i < nvalid) {
                rr[i] = r[s + i];
                vv[i] = v[s + i];
                bits |= (unsigned int)(m[s + i] & 1) << i;
            } else { rr[i] = 0.f; vv[i] = 0.f; }
        }
        vv[ITEMS] = 0.f;
    }
    g_bits[blockIdx.x * THREADS + t] = (unsigned char)bits;

    float4 f = tile_summary_rv(rr, vv, bits, nvalid);
    float4 sfx = warp_suffix_scan(f, lane);
    if (lane == 0) WAGG[w] = sfx;
    __syncthreads();
    if (w == 0) {                               // whole warp 0
        float4 sw = (lane < NWARPS) ? WAGG[lane] : ident4();
        sw = crosswarp_suffix_scan(sw, lane, NWARPS);
        if (lane == 0) g_blk[blockIdx.x] = sw;
        float4 ex = shfl_down4(sw, 1);
        if (lane >= NWARPS - 1) ex = ident4();
        // warp carry as affine of block carry: vt: ex.y + ex.x*c ; A: ex.w + ex.z*c
        if (lane < NWARPS) WC[lane] = make_float4(ex.y, ex.x, ex.w, ex.z);
    }
    __syncthreads();
    float4 wc = WC[w];
    float4 X = shfl_down4(sfx, 1);
    if (lane == 31) X = ident4();
    // thread carry as affine of block carry (both channels)
    float Pvt = X.y + X.x * wc.x;
    float Gvt = X.x * wc.y;
    float PA  = X.w + X.z * wc.z;
    float GA  = X.z * wc.w;
    g_tc[blockIdx.x * THREADS + t] = make_float4(Pvt, Gvt, PA, GA);

    float P = PA, G = GA;
    float sp = 0.f, sg = 0.f, spp = 0.f, spg = 0.f, sgg = 0.f;
#pragma unroll
    for (int i = ITEMS - 1; i >= 0; i--) {
        if (i < nvalid) {
            float a1 = a1_of(bits, i);
            float delta = rr[i] + a1 * vv[i + 1] - vv[i];
            float a2 = a1 * TAUF;
            P = delta + a2 * P;
            G = a2 * G;
            sp += P; sg += G;
            spp += P * P; spg += P * G; sgg += G * G;
        }
    }
#pragma unroll
    for (int d = 16; d > 0; d >>= 1) {
        sp  += __shfl_down_sync(0xffffffffu, sp, d);
        sg  += __shfl_down_sync(0xffffffffu, sg, d);
        spp += __shfl_down_sync(0xffffffffu, spp, d);
        spg += __shfl_down_sync(0xffffffffu, spg, d);
        sgg += __shfl_down_sync(0xffffffffu, sgg, d);
    }
    if (lane == 0) { SS0[w] = sp; SS1[w] = sg; SS2[w] = spp; SS3[w] = spg; SS4[w] = sgg; }
    __syncthreads();
    if (w == 0) {
        bool ok = lane < NWARPS;
        float a0 = ok ? SS0[lane] : 0.f;
        float a1 = ok ? SS1[lane] : 0.f;
        float a2 = ok ? SS2[lane] : 0.f;
        float a3 = ok ? SS3[lane] : 0.f;
        float a4 = ok ? SS4[lane] : 0.f;
#pragma unroll
        for (int d = NWARPS / 2; d > 0; d >>= 1) {
            a0 += __shfl_down_sync(0xffffffffu, a0, d);
            a1 += __shfl_down_sync(0xffffffffu, a1, d);
            a2 += __shfl_down_sync(0xffffffffu, a2, d);
            a3 += __shfl_down_sync(0xffffffffu, a3, d);
            a4 += __shfl_down_sync(0xffffffffu, a4, d);
        }
        if (lane == 0) {
            g_mA[blockIdx.x] = make_float4(a0, a1, a2, a3);
            g_mB[blockIdx.x] = a4;
        }
    }

    // allow pass3 to launch (its blocks wait idle at gridDepSync)
#if __CUDA_ARCH__ >= 900
    cudaTriggerProgrammaticLaunchCompletion();
#endif

    // ---- last-done block performs the (former) pass2 inline ----
    if (t == 0) {
        __threadfence();
        unsigned int dn = atomicAdd(&g_done, 1);
        LASTF = (dn == (unsigned int)NB - 1) ? 1 : 0;
    }
    __syncthreads();
    if (!LASTF) return;
    __threadfence();                            // all other blocks' writes visible

    int base = t * PER;
    float4 E = ident4();
#pragma unroll 1
    for (int i = 0; i < PER; i += 4) {          // batch loads for MLP
        int b = base + i;
        float4 f0 = (b + 0 < NB) ? g_blk[b + 0] : ident4();
        float4 f1 = (b + 1 < NB) ? g_blk[b + 1] : ident4();
        float4 f2 = (b + 2 < NB) ? g_blk[b + 2] : ident4();
        float4 f3 = (b + 3 < NB) ? g_blk[b + 3] : ident4();
        E = comp4(comp4(comp4(comp4(E, f0), f1), f2), f3);
    }
    float4 sfx2 = warp_suffix_scan(E, lane);
    if (lane == 0) WAGG[w] = sfx2;
    __syncthreads();
    if (w == 0) {
        float4 sw = (lane < NWARPS) ? WAGG[lane] : ident4();
        sw = crosswarp_suffix_scan(sw, lane, NWARPS);
        float4 ex = shfl_down4(sw, 1);
        if (lane >= NWARPS - 1) ex = ident4();
        if (lane < NWARPS) WC[lane] = make_float4(ex.y, ex.w, 0.f, 0.f);  // VALUE carries
    }
    __syncthreads();
    float4 wcar4 = WC[w];
    float2 wcar = make_float2(wcar4.x, wcar4.y);
    float4 X2 = shfl_down4(sfx2, 1);
    if (lane == 31) X2 = ident4();
    float2 V;                                   // carry entering block base+PER-1
    V.x = X2.y + X2.x * wcar.x;
    V.y = X2.w + X2.z * wcar.y;
    double dsum = 0.0, dssq = 0.0;
#pragma unroll 1
    for (int i = PER - 1; i >= 0; i -= 4) {     // batch payload loads for MLP
        int b3 = base + i;
        float4 mA0[4]; float mB0[4]; float4 fb0[4];
#pragma unroll
        for (int k = 0; k < 4; k++) {
            int b = b3 - 3 + k;
            bool ok = (b >= 0) && (b < NB);
            mA0[k] = ok ? g_mA[b] : make_float4(0.f, 0.f, 0.f, 0.f);
            mB0[k] = ok ? g_mB[b] : 0.f;
            fb0[k] = ok ? g_blk[b] : ident4();
        }
#pragma unroll
        for (int k = 3; k >= 0; k--) {
            int b = b3 - 3 + k;
            if (b >= 0 && b < NB) {
                g_carry[b] = V;
                float c = V.y;
                dsum += (double)(mA0[k].x + mA0[k].y * c);
                dssq += (double)(mA0[k].z + 2.f * mA0[k].w * c + mB0[k] * c * c);
                float2 nV;
                nV.x = fb0[k].y + fb0[k].x * V.x;
                nV.y = fb0[k].w + fb0[k].z * V.y;
                V = nV;
            }
        }
    }
#pragma unroll
    for (int d = 16; d > 0; d >>= 1) {
        dsum += __shfl_down_sync(0xffffffffu, dsum, d);
        dssq += __shfl_down_sync(0xffffffffu, dssq, d);
    }
    if (lane == 0) { DS[w] = dsum; DQ[w] = dssq; }
    __syncthreads();
    if (w == 0) {
        bool ok = lane < NWARPS;
        double sd = ok ? DS[lane] : 0.0;
        double qd = ok ? DQ[lane] : 0.0;
#pragma unroll
        for (int d = NWARPS / 2; d > 0; d >>= 1) {
            sd += __shfl_down_sync(0xffffffffu, sd, d);
            qd += __shfl_down_sync(0xffffffffu, qd, d);
        }
        if (lane == 0) {
            double mean = sd / (double)B;
            double var  = (qd - sd * mean) / (double)(B - 1);
            g_normc = make_float2((float)mean, (float)(1.0 / sqrt(var)));
            g_done = 0;                         // reset for next graph replay
        }
    }
}

// ---------------- Pass 3: NO scan, NO smem, NO syncthreads ----------------
__global__ void __launch_bounds__(THREADS, 8) k_pass3(const float* __restrict__ r,
                                                      const float* __restrict__ v,
                                                      float* __restrict__ outA,
                                                      float* __restrict__ outVT, long B) {
#if __CUDA_ARCH__ >= 900
    cudaGridDependencySynchronize();
#endif
    int t = threadIdx.x;
    long s = (long)blockIdx.x * CHUNK + (long)t * ITEMS;

    float rr[ITEMS], vv[ITEMS + 1];
    unsigned int bits = g_bits[blockIdx.x * THREADS + t];
    float4 tc = g_tc[blockIdx.x * THREADS + t];
    float2 cb = g_carry[blockIdx.x];
    float2 nc = g_normc;
    long rem = B - s;
    int nvalid = (rem >= ITEMS) ? ITEMS : (rem > 0 ? (int)rem : 0);
    if (nvalid == ITEMS) {
#pragma unroll
        for (int j = 0; j < ITEMS / 4; j++) {
            float4 x = *reinterpret_cast<const float4*>(r + s + 4 * j);
            float4 y = *reinterpret_cast<const float4*>(v + s + 4 * j);
            rr[4*j+0] = x.x; rr[4*j+1] = x.y; rr[4*j+2] = x.z; rr[4*j+3] = x.w;
            vv[4*j+0] = y.x; vv[4*j+1] = y.y; vv[4*j+2] = y.z; vv[4*j+3] = y.w;
        }
        vv[ITEMS] = (s + ITEMS < B) ? v[s + ITEMS] : 0.f;
    } else {
#pragma unroll
        for (int i = 0; i < ITEMS; i++) {
            if (i < nvalid) { rr[i] = r[s + i]; vv[i] = v[s + i]; }
            else { rr[i] = 0.f; vv[i] = 0.f; }
        }
        vv[ITEMS] = 0.f;
    }

    // thread carries directly from precomputed affine coefficients
    float cvt = tc.x + tc.y * cb.x;
    float ca  = tc.z + tc.w * cb.y;

    float mean = nc.x, istd = nc.y;
    // fixup: vt -> rr[i], A -> vv[i+1] (vv[i+1] dead after delta_i)
#pragma unroll
    for (int i = ITEMS - 1; i >= 0; i--) {
        if (i < nvalid) {
            float a1 = a1_of(bits, i);
            float delta = rr[i] + a1 * vv[i + 1] - vv[i];
            float vt = rr[i] + a1 * cvt;
            float A  = delta + a1 * TAUF * ca;
            rr[i] = vt;
            vv[i + 1] = A;
            cvt = vt; ca = A;
        }
    }
    if (nvalid == ITEMS) {
        __stcs(reinterpret_cast<float4*>(outVT + s), make_float4(rr[0], rr[1], rr[2], rr[3]));
        __stcs(reinterpret_cast<float4*>(outVT + s + 4), make_float4(rr[4], rr[5], rr[6], rr[7]));
        __stcs(reinterpret_cast<float4*>(outA + s),
               make_float4((vv[1] - mean) * istd, (vv[2] - mean) * istd,
                           (vv[3] - mean) * istd, (vv[4] - mean) * istd));
        __stcs(reinterpret_cast<float4*>(outA + s + 4),
               make_float4((vv[5] - mean) * istd, (vv[6] - mean) * istd,
                           (vv[7] - mean) * istd, (vv[8] - mean) * istd));
    } else {
#pragma unroll
        for (int i = 0; i < ITEMS; i++) {
            if (i < nvalid) {
                outVT[s + i] = rr[i];
                outA[s + i]  = (vv[i + 1] - mean) * istd;
            }
        }
    }
}

extern "C" void kernel_launch(void* const* d_in, const int* in_sizes, int n_in,
                              void* d_out, int out_size) {
    const float* r = (const float*)d_in[0];
    const float* v = (const float*)d_in[1];
    const int*   m = (const int*)d_in[2];
    long B = (long)in_sizes[0];
    float* outA  = (float*)d_out;
    float* outVT = outA + B;

    int NB = (int)((B + CHUNK - 1) / CHUNK);
    if (NB > NB_MAX) NB = NB_MAX;   // this problem: B=4194304 -> NB=2048

    k_pass1<<<NB, THREADS>>>(r, v, m, B, NB);

    // PDL launch: pass3 blocks start early but gridDepSync FIRST (idle wait).
    cudaLaunchConfig_t cfg = {};
    cfg.gridDim = dim3((unsigned)NB, 1, 1);
    cfg.blockDim = dim3(THREADS, 1, 1);
    cfg.dynamicSmemBytes = 0;
    cfg.stream = 0;
    cudaLaunchAttribute attrs[1];
    attrs[0].id = cudaLaunchAttributeProgrammaticStreamSerialization;
    attrs[0].val.programmaticStreamSerializationAllowed = 1;
    cfg.attrs = attrs;
    cfg.numAttrs = 1;
    cudaLaunchKernelEx(&cfg, k_pass3, r, v, outA, outVT, B);
}

// round 15
// speedup vs baseline: 1.2778x; 1.0026x over previous
#include <cuda_runtime.h>
#include <math.h>

#define GAMMA 0.99f
#define TAUF  0.95f

constexpr int THREADS = 256;
constexpr int ITEMS   = 8;
constexpr int CHUNK   = THREADS * ITEMS;   // 2048
constexpr int NWARPS  = THREADS / 32;      // 8
constexpr int PER     = 8;                 // summaries per thread in fused pass2
constexpr int NB_MAX  = THREADS * PER;     // 2048 blocks max (B <= 4,194,304)

// Scratch (device globals; no allocation allowed)
__device__ float4 g_blk[NB_MAX];     // per-block affine summary: (a_vt, b_vt, a_A, b_A)
__device__ float2 g_carry[NB_MAX];   // per-block incoming carry VALUES (vt, A)
__device__ float4 g_mA[NB_MAX];      // per-block (SP, SG, SPP, SPG)
__device__ float  g_mB[NB_MAX];      // per-block SGG
__device__ unsigned char g_bits[NB_MAX * THREADS];  // packed masks, 1 byte per thread-tile
__device__ float4 g_tc[NB_MAX * THREADS];  // per-thread carry coeffs (Pvt, Gvt, PA, GA)
__device__ float2 g_normc;           // (mean, inv_std)
__device__ unsigned int g_done = 0;  // finish counter (reset by last block)

__device__ __forceinline__ float4 ident4() { return make_float4(1.f, 0.f, 1.f, 0.f); }

// lo covers lower (earlier) indices; carry flows high->low: result = f_lo(f_hi(c))
__device__ __forceinline__ float4 comp4(float4 lo, float4 hi) {
    float4 o;
    o.x = lo.x * hi.x;
    o.y = lo.y + lo.x * hi.y;
    o.z = lo.z * hi.z;
    o.w = lo.w + lo.z * hi.w;
    return o;
}

__device__ __forceinline__ float4 shfl_down4(float4 v, int d) {
    float4 o;
    o.x = __shfl_down_sync(0xffffffffu, v.x, d);
    o.y = __shfl_down_sync(0xffffffffu, v.y, d);
    o.z = __shfl_down_sync(0xffffffffu, v.z, d);
    o.w = __shfl_down_sync(0xffffffffu, v.w, d);
    return o;
}

// Inclusive SUFFIX scan within a warp; ALL 32 lanes execute.
__device__ __forceinline__ float4 warp_suffix_scan(float4 v, int lane) {
#pragma unroll
    for (int d = 1; d < 32; d <<= 1) {
        float4 o = shfl_down4(v, d);
        if (lane + d < 32) v = comp4(v, o);
    }
    return v;
}

__device__ __forceinline__ float4 crosswarp_suffix_scan(float4 v, int lane, int n) {
#pragma unroll
    for (int d = 1; d < 32; d <<= 1) {
        if (d >= n) break;
        float4 o = shfl_down4(v, d);
        if (lane + d < n) v = comp4(v, o);
    }
    return v;
}

__device__ __forceinline__ float a1_of(unsigned int bits, int i) {
    return ((bits >> i) & 1u) ? GAMMA : 0.f;
}

// Tile summary from (rr, vv, bits): forward composition (F = f_0 o f_1 o ...)
__device__ __forceinline__ float4 tile_summary_rv(const float* rr, const float* vv,
                                                  unsigned int bits, int nvalid) {
    float av = 1.f, bv = 0.f, aa = 1.f, ba = 0.f;
#pragma unroll
    for (int i = 0; i < ITEMS; i++) {
        if (i < nvalid) {
            float a1 = a1_of(bits, i);
            float delta = rr[i] + a1 * vv[i + 1] - vv[i];
            float a2 = a1 * TAUF;
            bv = bv + av * rr[i]; av = av * a1;
            ba = ba + aa * delta; aa = aa * a2;
        }
    }
    return make_float4(av, bv, aa, ba);
}

// ---------------- Pass 1: summaries + per-thread carry coeffs + moments ----------------
__global__ void __launch_bounds__(THREADS) k_pass1(const float* __restrict__ r,
                                                   const float* __restrict__ v,
                                                   const int* __restrict__ m,
                                                   long B, int NB) {
    __shared__ float4 WAGG[NWARPS];
    __shared__ float4 WC[NWARPS];               // (Pvt, Gvt, PA, GA) per warp
    __shared__ float SS0[NWARPS], SS1[NWARPS], SS2[NWARPS], SS3[NWARPS], SS4[NWARPS];
    __shared__ int LASTF;
    __shared__ double DS[NWARPS], DQ[NWARPS];
    int t = threadIdx.x, lane = t & 31, w = t >> 5;
    long s = (long)blockIdx.x * CHUNK + (long)t * ITEMS;

    float rr[ITEMS], vv[ITEMS + 1];
    unsigned int bits = 0;
    long rem = B - s;
    int nvalid = (rem >= ITEMS) ? ITEMS : (rem > 0 ? (int)rem : 0);
    if (nvalid == ITEMS) {
#pragma unroll
        for (int j = 0; j < ITEMS / 4; j++) {
            float4 x = *reinterpret_cast<const float4*>(r + s + 4 * j);
            float4 y = *reinterpret_cast<const float4*>(v + s + 4 * j);
            int4  mi = *reinterpret_cast<const int4*>(m + s + 4 * j);
            rr[4*j+0] = x.x; rr[4*j+1] = x.y; rr[4*j+2] = x.z; rr[4*j+3] = x.w;
            vv[4*j+0] = y.x; vv[4*j+1] = y.y; vv[4*j+2] = y.z; vv[4*j+3] = y.w;
            bits |= (unsigned int)(mi.x & 1) << (4*j+0);
            bits |= (unsigned int)(mi.y & 1) << (4*j+1);
            bits |= (unsigned int)(mi.z & 1) << (4*j+2);
            bits |= (unsigned int)(mi.w & 1) << (4*j+3);
        }
        vv[ITEMS] = (s + ITEMS < B) ? v[s + ITEMS] : 0.f;
    } else {
#pragma unroll
        for (int i = 0; i < ITEMS; i++) {
            if (i < nvalid) {
                rr[i] = r[s + i];
                vv[i] = v[s + i];
                bits |= (unsigned int)(m[s + i] & 1) << i;
            } else { rr[i] = 0.f; vv[i] = 0.f; }
        }
        vv[ITEMS] = 0.f;
    }
    g_bits[blockIdx.x * THREADS + t] = (unsigned char)bits;

    float4 f = tile_summary_rv(rr, vv, bits, nvalid);
    float4 sfx = warp_suffix_scan(f, lane);
    if (lane == 0) WAGG[w] = sfx;
    __syncthreads();
    if (w == 0) {                               // whole warp 0
        float4 sw = (lane < NWARPS) ? WAGG[lane] : ident4();
        sw = crosswarp_suffix_scan(sw, lane, NWARPS);
        if (lane == 0) g_blk[blockIdx.x] = sw;
        float4 ex = shfl_down4(sw, 1);
        if (lane >= NWARPS - 1) ex = ident4();
        // warp carry as affine of block carry: vt: ex.y + ex.x*c ; A: ex.w + ex.z*c
        if (lane < NWARPS) WC[lane] = make_float4(ex.y, ex.x, ex.w, ex.z);
    }
    __syncthreads();
    float4 wc = WC[w];
    float4 X = shfl_down4(sfx, 1);
    if (lane == 31) X = ident4();
    // thread carry as affine of block carry (both channels)
    float Pvt = X.y + X.x * wc.x;
    float Gvt = X.x * wc.y;
    float PA  = X.w + X.z * wc.z;
    float GA  = X.z * wc.w;
    g_tc[blockIdx.x * THREADS + t] = make_float4(Pvt, Gvt, PA, GA);

    float P = PA, G = GA;
    float sp = 0.f, sg = 0.f, spp = 0.f, spg = 0.f, sgg = 0.f;
#pragma unroll
    for (int i = ITEMS - 1; i >= 0; i--) {
        if (i < nvalid) {
            float a1 = a1_of(bits, i);
            float delta = rr[i] + a1 * vv[i + 1] - vv[i];
            float a2 = a1 * TAUF;
            P = delta + a2 * P;
            G = a2 * G;
            sp += P; sg += G;
            spp += P * P; spg += P * G; sgg += G * G;
        }
    }
#pragma unroll
    for (int d = 16; d > 0; d >>= 1) {
        sp  += __shfl_down_sync(0xffffffffu, sp, d);
        sg  += __shfl_down_sync(0xffffffffu, sg, d);
        spp += __shfl_down_sync(0xffffffffu, spp, d);
        spg += __shfl_down_sync(0xffffffffu, spg, d);
        sgg += __shfl_down_sync(0xffffffffu, sgg, d);
    }
    if (lane == 0) { SS0[w] = sp; SS1[w] = sg; SS2[w] = spp; SS3[w] = spg; SS4[w] = sgg; }
    __syncthreads();
    if (w == 0) {
        bool ok = lane < NWARPS;
        float a0 = ok ? SS0[lane] : 0.f;
        float a1 = ok ? SS1[lane] : 0.f;
        float a2 = ok ? SS2[lane] : 0.f;
        float a3 = ok ? SS3[lane] : 0.f;
        float a4 = ok ? SS4[lane] : 0.f;
#pragma unroll
        for (int d = NWARPS / 2; d > 0; d >>= 1) {
            a0 += __shfl_down_sync(0xffffffffu, a0, d);
            a1 += __shfl_down_sync(0xffffffffu, a1, d);
            a2 += __shfl_down_sync(0xffffffffu, a2, d);
            a3 += __shfl_down_sync(0xffffffffu, a3, d);
            a4 += __shfl_down_sync(0xffffffffu, a4, d);
        }
        if (lane == 0) {
            g_mA[blockIdx.x] = make_float4(a0, a1, a2, a3);
            g_mB[blockIdx.x] = a4;
        }
    }

    // allow pass3 to launch (its blocks wait idle at gridDepSync)
#if __CUDA_ARCH__ >= 900
    cudaTriggerProgrammaticLaunchCompletion();
#endif

    // ---- last-done block performs the (former) pass2 inline ----
    if (t == 0) {
        __threadfence();
        unsigned int dn = atomicAdd(&g_done, 1);
        LASTF = (dn == (unsigned int)NB - 1) ? 1 : 0;
    }
    __syncthreads();
    if (!LASTF) return;
    __threadfence();                            // all other blocks' writes visible

    int base = t * PER;
    float4 E = ident4();
#pragma unroll 1
    for (int i = 0; i < PER; i += 4) {          // batch loads for MLP
        int b = base + i;
        float4 f0 = (b + 0 < NB) ? g_blk[b + 0] : ident4();
        float4 f1 = (b + 1 < NB) ? g_blk[b + 1] : ident4();
        float4 f2 = (b + 2 < NB) ? g_blk[b + 2] : ident4();
        float4 f3 = (b + 3 < NB) ? g_blk[b + 3] : ident4();
        E = comp4(comp4(comp4(comp4(E, f0), f1), f2), f3);
    }
    float4 sfx2 = warp_suffix_scan(E, lane);
    if (lane == 0) WAGG[w] = sfx2;
    __syncthreads();
    if (w == 0) {
        float4 sw = (lane < NWARPS) ? WAGG[lane] : ident4();
        sw = crosswarp_suffix_scan(sw, lane, NWARPS);
        float4 ex = shfl_down4(sw, 1);
        if (lane >= NWARPS - 1) ex = ident4();
        if (lane < NWARPS) WC[lane] = make_float4(ex.y, ex.w, 0.f, 0.f);  // VALUE carries
    }
    __syncthreads();
    float4 wcar4 = WC[w];
    float2 wcar = make_float2(wcar4.x, wcar4.y);
    float4 X2 = shfl_down4(sfx2, 1);
    if (lane == 31) X2 = ident4();
    float2 V;                                   // carry entering block base+PER-1
    V.x = X2.y + X2.x * wcar.x;
    V.y = X2.w + X2.z * wcar.y;
    double dsum = 0.0, dssq = 0.0;
#pragma unroll 1
    for (int i = PER - 1; i >= 0; i -= 4) {     // batch payload loads for MLP
        int b3 = base + i;
        float4 mA0[4]; float mB0[4]; float4 fb0[4];
#pragma unroll
        for (int k = 0; k < 4; k++) {
            int b = b3 - 3 + k;
            bool ok = (b >= 0) && (b < NB);
            mA0[k] = ok ? g_mA[b] : make_float4(0.f, 0.f, 0.f, 0.f);
            mB0[k] = ok ? g_mB[b] : 0.f;
            fb0[k] = ok ? g_blk[b] : ident4();
        }
#pragma unroll
        for (int k = 3; k >= 0; k--) {
            int b = b3 - 3 + k;
            if (b >= 0 && b < NB) {
                g_carry[b] = V;
                float c = V.y;
                dsum += (double)(mA0[k].x + mA0[k].y * c);
                dssq += (double)(mA0[k].z + 2.f * mA0[k].w * c + mB0[k] * c * c);
                float2 nV;
                nV.x = fb0[k].y + fb0[k].x * V.x;
                nV.y = fb0[k].w + fb0[k].z * V.y;
                V = nV;
            }
        }
    }
#pragma unroll
    for (int d = 16; d > 0; d >>= 1) {
        dsum += __shfl_down_sync(0xffffffffu, dsum, d);
        dssq += __shfl_down_sync(0xffffffffu, dssq, d);
    }
    if (lane == 0) { DS[w] = dsum; DQ[w] = dssq; }
    __syncthreads();
    if (w == 0) {
        bool ok = lane < NWARPS;
        double sd = ok ? DS[lane] : 0.0;
        double qd = ok ? DQ[lane] : 0.0;
#pragma unroll
        for (int d = NWARPS / 2; d > 0; d >>= 1) {
            sd += __shfl_down_sync(0xffffffffu, sd, d);
            qd += __shfl_down_sync(0xffffffffu, qd, d);
        }
        if (lane == 0) {
            double mean = sd / (double)B;
            double var  = (qd - sd * mean) / (double)(B - 1);
            g_normc = make_float2((float)mean, (float)(1.0 / sqrt(var)));
            g_done = 0;                         // reset for next graph replay
        }
    }
}

// ---------------- Pass 3: 2 independent tiles per thread, no scan, normal stores ----------------
__global__ void __launch_bounds__(THREADS, 4) k_pass3(const float* __restrict__ r,
                                                      const float* __restrict__ v,
                                                      float* __restrict__ outA,
                                                      float* __restrict__ outVT,
                                                      long B, int NB) {
#if __CUDA_ARCH__ >= 900
    cudaGridDependencySynchronize();
#endif
    int t = threadIdx.x;
    int b0 = 2 * blockIdx.x;
    int b1 = b0 + 1;
    long s0 = (long)b0 * CHUNK + (long)t * ITEMS;
    long s1 = s0 + CHUNK;

    float2 nc = g_normc;
    float mean = nc.x, istd = nc.y;

    // ---- tile metadata (small loads first; independent) ----
    unsigned int bits0 = g_bits[b0 * THREADS + t];
    float4 tc0 = g_tc[b0 * THREADS + t];
    float2 cb0 = g_carry[b0];
    unsigned int bits1 = 0;
    float4 tc1 = make_float4(0.f, 0.f, 0.f, 0.f);
    float2 cb1 = make_float2(0.f, 0.f);
    bool has1 = (b1 < NB);
    if (has1) {
        bits1 = g_bits[b1 * THREADS + t];
        tc1 = g_tc[b1 * THREADS + t];
        cb1 = g_carry[b1];
    }

    long rem0 = B - s0;
    int nv0 = (rem0 >= ITEMS) ? ITEMS : (rem0 > 0 ? (int)rem0 : 0);
    long rem1 = B - s1;
    int nv1 = has1 ? ((rem1 >= ITEMS) ? ITEMS : (rem1 > 0 ? (int)rem1 : 0)) : 0;

    // ---- bulk loads for both tiles (interleaved for MLP) ----
    float rr0[ITEMS], vv0[ITEMS + 1], rr1[ITEMS], vv1[ITEMS + 1];
    if (nv0 == ITEMS) {
#pragma unroll
        for (int j = 0; j < ITEMS / 4; j++) {
            float4 x = *reinterpret_cast<const float4*>(r + s0 + 4 * j);
            float4 y = *reinterpret_cast<const float4*>(v + s0 + 4 * j);
            rr0[4*j+0] = x.x; rr0[4*j+1] = x.y; rr0[4*j+2] = x.z; rr0[4*j+3] = x.w;
            vv0[4*j+0] = y.x; vv0[4*j+1] = y.y; vv0[4*j+2] = y.z; vv0[4*j+3] = y.w;
        }
        vv0[ITEMS] = (s0 + ITEMS < B) ? v[s0 + ITEMS] : 0.f;
    } else {
#pragma unroll
        for (int i = 0; i < ITEMS; i++) {
            if (i < nv0) { rr0[i] = r[s0 + i]; vv0[i] = v[s0 + i]; }
            else { rr0[i] = 0.f; vv0[i] = 0.f; }
        }
        vv0[ITEMS] = 0.f;
    }
    if (nv1 == ITEMS) {
#pragma unroll
        for (int j = 0; j < ITEMS / 4; j++) {
            float4 x = *reinterpret_cast<const float4*>(r + s1 + 4 * j);
            float4 y = *reinterpret_cast<const float4*>(v + s1 + 4 * j);
            rr1[4*j+0] = x.x; rr1[4*j+1] = x.y; rr1[4*j+2] = x.z; rr1[4*j+3] = x.w;
            vv1[4*j+0] = y.x; vv1[4*j+1] = y.y; vv1[4*j+2] = y.z; vv1[4*j+3] = y.w;
        }
        vv1[ITEMS] = (s1 + ITEMS < B) ? v[s1 + ITEMS] : 0.f;
    } else {
#pragma unroll
        for (int i = 0; i < ITEMS; i++) {
            if (i < nv1) { rr1[i] = r[s1 + i]; vv1[i] = v[s1 + i]; }
            else { rr1[i] = 0.f; vv1[i] = 0.f; }
        }
        vv1[ITEMS] = 0.f;
    }

    // ---- two independent fixup chains (interleaved by the compiler) ----
    float cvt0 = tc0.x + tc0.y * cb0.x;
    float ca0  = tc0.z + tc0.w * cb0.y;
    float cvt1 = tc1.x + tc1.y * cb1.x;
    float ca1  = tc1.z + tc1.w * cb1.y;
#pragma unroll
    for (int i = ITEMS - 1; i >= 0; i--) {
        if (i < nv0) {
            float a1 = a1_of(bits0, i);
            float delta = rr0[i] + a1 * vv0[i + 1] - vv0[i];
            float vt = rr0[i] + a1 * cvt0;
            float A  = delta + a1 * TAUF * ca0;
            rr0[i] = vt; vv0[i + 1] = A;
            cvt0 = vt; ca0 = A;
        }
        if (i < nv1) {
            float a1 = a1_of(bits1, i);
            float delta = rr1[i] + a1 * vv1[i + 1] - vv1[i];
            float vt = rr1[i] + a1 * cvt1;
            float A  = delta + a1 * TAUF * ca1;
            rr1[i] = vt; vv1[i + 1] = A;
            cvt1 = vt; ca1 = A;
        }
    }

    // ---- stores ----
    if (nv0 == ITEMS) {
        *reinterpret_cast<float4*>(outVT + s0) = make_float4(rr0[0], rr0[1], rr0[2], rr0[3]);
        *reinterpret_cast<float4*>(outVT + s0 + 4) = make_float4(rr0[4], rr0[5], rr0[6], rr0[7]);
        *reinterpret_cast<float4*>(outA + s0) =
            make_float4((vv0[1] - mean) * istd, (vv0[2] - mean) * istd,
                        (vv0[3] - mean) * istd, (vv0[4] - mean) * istd);
        *reinterpret_cast<float4*>(outA + s0 + 4) =
            make_float4((vv0[5] - mean) * istd, (vv0[6] - mean) * istd,
                        (vv0[7] - mean) * istd, (vv0[8] - mean) * istd);
    } else {
#pragma unroll
        for (int i = 0; i < ITEMS; i++) {
            if (i < nv0) {
                outVT[s0 + i] = rr0[i];
                outA[s0 + i]  = (vv0[i + 1] - mean) * istd;
            }
        }
    }
    if (nv1 == ITEMS) {
        *reinterpret_cast<float4*>(outVT + s1) = make_float4(rr1[0], rr1[1], rr1[2], rr1[3]);
        *reinterpret_cast<float4*>(outVT + s1 + 4) = make_float4(rr1[4], rr1[5], rr1[6], rr1[7]);
        *reinterpret_cast<float4*>(outA + s1) =
            make_float4((vv1[1] - mean) * istd, (vv1[2] - mean) * istd,
                        (vv1[3] - mean) * istd, (vv1[4] - mean) * istd);
        *reinterpret_cast<float4*>(outA + s1 + 4) =
            make_float4((vv1[5] - mean) * istd, (vv1[6] - mean) * istd,
                        (vv1[7] - mean) * istd, (vv1[8] - mean) * istd);
    } else {
#pragma unroll
        for (int i = 0; i < ITEMS; i++) {
            if (i < nv1) {
                outVT[s1 + i] = rr1[i];
                outA[s1 + i]  = (vv1[i + 1] - mean) * istd;
            }
        }
    }
}

extern "C" void kernel_launch(void* const* d_in, const int* in_sizes, int n_in,
                              void* d_out, int out_size) {
    const float* r = (const float*)d_in[0];
    const float* v = (const float*)d_in[1];
    const int*   m = (const int*)d_in[2];
    long B = (long)in_sizes[0];
    float* outA  = (float*)d_out;
    float* outVT = outA + B;

    int NB = (int)((B + CHUNK - 1) / CHUNK);
    if (NB > NB_MAX) NB = NB_MAX;   // this problem: B=4194304 -> NB=2048

    k_pass1<<<NB, THREADS>>>(r, v, m, B, NB);

    int NB3 = (NB + 1) / 2;
    // PDL launch: pass3 blocks start early but gridDepSync FIRST (idle wait).
    cudaLaunchConfig_t cfg = {};
    cfg.gridDim = dim3((unsigned)NB3, 1, 1);
    cfg.blockDim = dim3(THREADS, 1, 1);
    cfg.dynamicSmemBytes = 0;
    cfg.stream = 0;
    cudaLaunchAttribute attrs[1];
    attrs[0].id = cudaLaunchAttributeProgrammaticStreamSerialization;
    attrs[0].val.programmaticStreamSerializationAllowed = 1;
    cfg.attrs = attrs;
    cfg.numAttrs = 1;
    cudaLaunchKernelEx(&cfg, k_pass3, r, v, outA, outVT, B, NB);
}